// round 7
// baseline (speedup 1.0000x reference)
#include <cuda_runtime.h>
#include <cuda_bf16.h>
#include <cstdint>

#define HID   256
#define LAT   128
#define ODIM  128
#define NBLK  4
#define NIT   10
#define TM    128
#define NTHR  256
#define KC    32

// ---------------- SMEM layout (bytes) ----------------
#define SM_AHI   1024
#define SM_ALO   (1024 + 65536)
#define SM_B     (1024 + 2 * 65536)          // 132096
#define B_STG_H  32768                       // hidden GEMM stage (N=256)
#define B_STG_F  16384                       // final GEMM stage (N=128)
#define SM_BYTES (SM_B + 2 * B_STG_H)        // 197632
// control region: [0] tmem ptr, [16],[24] mbarriers

// ---------------- pre-processed weight blob ----------------
// layout per matrix: stages of KC=32 K; each stage is the exact SMEM image:
// N rows x 128B; bytes [0,64) = bf16 hi of 32 K, [64,128) = bf16 lo; SW128 swizzled.
#define WB_INIT  0u
#define WB_G1(b) (131072u + (unsigned)(b) * 262144u)
#define WB_G2(b) (1179648u + (unsigned)(b) * 262144u)
#define WB_FIN   2228224u
__device__ __align__(128) unsigned char g_wblob[2359296];

#define IDESC_N256 0x8400490u   // f32 acc, bf16 x bf16, M=128, N=256
#define IDESC_N128 0x8200490u   // f32 acc, bf16 x bf16, M=128, N=128

static constexpr uint64_t DESC_BASE_SW128 =
    (uint64_t(2) << 61) | (uint64_t(1) << 46) | (uint64_t(64) << 32) | (uint64_t(1) << 16);

// tcgen05 is arch-SPECIFIC (sm_103a): the harness also runs a compute_103
// (family) ptxas pass which rejects it. Gate every tcgen05 instruction on the
// arch-specific feature macros; the base pass gets stubs that never execute
// (the fatbin's exact-match sm_103a SASS is what runs on the GB300).
#if defined(__CUDA_ARCH__) && \
    (defined(__CUDA_ARCH_FEAT_SM103_ALL) || defined(__CUDA_ARCH_FEAT_SM100_ALL) || \
     defined(__CUDA_ARCH_FEAT_SM101_ALL) || defined(__CUDA_ARCH_SPECIFIC__))
#define TC_OK 1
#else
#define TC_OK 0
#endif

// ---------------- PTX helpers ----------------
static __device__ __forceinline__ uint32_t smem_u32(const void* p) {
    uint32_t a;
    asm("{ .reg .u64 t; cvta.to.shared.u64 t, %1; cvt.u32.u64 %0, t; }" : "=r"(a) : "l"(p));
    return a;
}
static __device__ __forceinline__ uint32_t elect1() {
    uint32_t p;
    asm volatile("{ .reg .pred p; elect.sync _|p, 0xFFFFFFFF; selp.b32 %0, 1, 0, p; }" : "=r"(p));
    return p;
}
static __device__ __forceinline__ uint64_t mk_desc(uint32_t addr) {
    return DESC_BASE_SW128 | ((uint64_t)(addr >> 4) & 0x3FFF);
}

#if TC_OK
static __device__ __forceinline__ void mma_ss(uint32_t d, uint64_t ad, uint64_t bd,
                                              uint32_t idesc, uint32_t en) {
    asm volatile(
        "{\n\t.reg .pred p;\n\tsetp.ne.u32 p, %4, 0;\n\t"
        "tcgen05.mma.cta_group::1.kind::f16 [%0], %1, %2, %3, {%5, %5, %5, %5}, p;\n\t}"
        :: "r"(d), "l"(ad), "l"(bd), "r"(idesc), "r"(en), "r"(0u) : "memory");
}
#define TC_COMMIT(mb) \
    asm volatile("tcgen05.commit.cta_group::1.mbarrier::arrive::one.shared::cluster.b64 [%0];" \
                 :: "r"(mb) : "memory")
#define TC_FENCE_AFTER()   asm volatile("tcgen05.fence::after_thread_sync;" ::: "memory")
#define TC_FENCE_BEFORE()  asm volatile("tcgen05.fence::before_thread_sync;" ::: "memory")
#define TC_WAIT_LD()   asm volatile("tcgen05.wait::ld.sync.aligned;" ::: "memory")
#define TC_WAIT_ST()   asm volatile("tcgen05.wait::st.sync.aligned;" ::: "memory")
#define TC_ALLOC(sa, n) \
    asm volatile("tcgen05.alloc.cta_group::1.sync.aligned.shared::cta.b32 [%0], %1;" \
                 :: "r"(sa), "r"((uint32_t)(n)) : "memory")
#define TC_DEALLOC(t, n) \
    asm volatile("tcgen05.dealloc.cta_group::1.sync.aligned.b32 %0, %1;" :: "r"(t), "r"((uint32_t)(n)))
#define TC_RELINQ() \
    asm volatile("tcgen05.relinquish_alloc_permit.cta_group::1.sync.aligned;")

#define LDTM32(r, a)                                                                    \
    asm volatile("tcgen05.ld.sync.aligned.32x32b.x32.b32 "                              \
        "{%0,%1,%2,%3,%4,%5,%6,%7,%8,%9,%10,%11,%12,%13,%14,%15,"                       \
        "%16,%17,%18,%19,%20,%21,%22,%23,%24,%25,%26,%27,%28,%29,%30,%31}, [%32];"      \
        : "=r"((r)[0]),"=r"((r)[1]),"=r"((r)[2]),"=r"((r)[3]),"=r"((r)[4]),"=r"((r)[5]),\
          "=r"((r)[6]),"=r"((r)[7]),"=r"((r)[8]),"=r"((r)[9]),"=r"((r)[10]),"=r"((r)[11]),\
          "=r"((r)[12]),"=r"((r)[13]),"=r"((r)[14]),"=r"((r)[15]),"=r"((r)[16]),"=r"((r)[17]),\
          "=r"((r)[18]),"=r"((r)[19]),"=r"((r)[20]),"=r"((r)[21]),"=r"((r)[22]),"=r"((r)[23]),\
          "=r"((r)[24]),"=r"((r)[25]),"=r"((r)[26]),"=r"((r)[27]),"=r"((r)[28]),"=r"((r)[29]),\
          "=r"((r)[30]),"=r"((r)[31]) : "r"(a))

#define STTM32(a, r)                                                                    \
    asm volatile("tcgen05.st.sync.aligned.32x32b.x32.b32 [%0], "                        \
        "{%1,%2,%3,%4,%5,%6,%7,%8,%9,%10,%11,%12,%13,%14,%15,%16,"                      \
        "%17,%18,%19,%20,%21,%22,%23,%24,%25,%26,%27,%28,%29,%30,%31,%32};"             \
        :: "r"(a), "r"((r)[0]),"r"((r)[1]),"r"((r)[2]),"r"((r)[3]),"r"((r)[4]),"r"((r)[5]),\
           "r"((r)[6]),"r"((r)[7]),"r"((r)[8]),"r"((r)[9]),"r"((r)[10]),"r"((r)[11]),   \
           "r"((r)[12]),"r"((r)[13]),"r"((r)[14]),"r"((r)[15]),"r"((r)[16]),"r"((r)[17]),\
           "r"((r)[18]),"r"((r)[19]),"r"((r)[20]),"r"((r)[21]),"r"((r)[22]),"r"((r)[23]),\
           "r"((r)[24]),"r"((r)[25]),"r"((r)[26]),"r"((r)[27]),"r"((r)[28]),"r"((r)[29]),\
           "r"((r)[30]),"r"((r)[31]) : "memory")
#else
// Stubs for the non-arch-specific (compute_103 family) compile pass.
// This code path never executes on the GB300 (sm_103a SASS is exact-match).
static __device__ __forceinline__ void mma_ss(uint32_t, uint64_t, uint64_t, uint32_t, uint32_t) {}
#define TC_COMMIT(mb)      do { (void)(mb); } while (0)
#define TC_FENCE_AFTER()   do {} while (0)
#define TC_FENCE_BEFORE()  do {} while (0)
#define TC_WAIT_LD()       do {} while (0)
#define TC_WAIT_ST()       do {} while (0)
#define TC_ALLOC(sa, n)    do { (void)(sa); (void)(n); } while (0)
#define TC_DEALLOC(t, n)   do { (void)(t); (void)(n); } while (0)
#define TC_RELINQ()        do {} while (0)
#define LDTM32(r, a)       do { _Pragma("unroll") for (int _i = 0; _i < 32; _i++) (r)[_i] = 0u; (void)(a); } while (0)
#define STTM32(a, r)       do { (void)(a); (void)(r); } while (0)
#endif

#define MBAR_INIT(a) \
    asm volatile("mbarrier.init.shared.b64 [%0], %1;" :: "r"(a), "r"(1u) : "memory")
#define MBAR_INVAL(a) \
    asm volatile("mbarrier.inval.shared.b64 [%0];" :: "r"(a) : "memory")
#define MBAR_WAIT(a, ph) do {                                                          \
    asm volatile("{\n\t.reg .pred P;\nWL_%=:\n\t"                                      \
        "mbarrier.try_wait.parity.acquire.cta.shared::cta.b64 P, [%0], %1, 0x989680;\n\t" \
        "@P bra.uni WD_%=;\n\tbra.uni WL_%=;\nWD_%=:\n\t}"                             \
        :: "r"(a), "r"((uint32_t)(ph)) : "memory");                                    \
} while (0)
#define FENCE_ASYNC()  asm volatile("fence.proxy.async.shared::cta;" ::: "memory")

// A-operand blocked-atom + SW128 byte address for (row m, k element)
static __device__ __forceinline__ uint32_t a_addr(int m, int k) {
    uint32_t off = (uint32_t)(((m >> 3) + (k >> 6) * 16) * 1024 + (m & 7) * 128 + (k & 63) * 2);
    return off ^ ((off >> 3) & 0x70);
}
static __device__ __forceinline__ void split_bf(float v, unsigned short& h, unsigned short& l) {
    __nv_bfloat16 hb = __float2bfloat16(v);
    float hf = __bfloat162float(hb);
    __nv_bfloat16 lb = __float2bfloat16(v - hf);
    h = *reinterpret_cast<unsigned short*>(&hb);
    l = *reinterpret_cast<unsigned short*>(&lb);
}
static __device__ __forceinline__ float bfu2f(uint32_t us) {
    return __uint_as_float((us & 0xFFFFu) << 16);
}

// ---------------- weight prep kernel ----------------
// W is [K, N] row-major fp32 (as used by h @ W). Produce stage-major SMEM images
// of B = W^T ([N, K] K-major), split hi/lo bf16, SW128 swizzled.
__global__ void prep_w(const float* __restrict__ W, int K, int N, unsigned blob_off) {
    int idx = blockIdx.x * blockDim.x + threadIdx.x;
    if (idx >= K * N) return;
    int k = idx / N, n = idx % N;
    float w = W[idx];
    unsigned short hs, ls;
    split_bf(w, hs, ls);
    int stage = k >> 5, kl = k & 31;
    unsigned row = (unsigned)((n >> 3) * 1024 + (n & 7) * 128);
    unsigned oh = row + kl * 2;
    unsigned ol = row + (32 + kl) * 2;
    oh ^= (oh >> 3) & 0x70;
    ol ^= (ol >> 3) & 0x70;
    unsigned char* sb = g_wblob + blob_off + (size_t)stage * ((size_t)N * 128);
    *(unsigned short*)(sb + oh) = hs;
    *(unsigned short*)(sb + ol) = ls;
}

// ---------------- main kernel pieces ----------------

// GEMM: D(TMEM cols 0..N) = A(hi/lo in SMEM) x B(streamed stages), 3-term split-bf16.
static __device__ void run_gemm(char* sm, uint32_t smb, uint32_t tmem,
                                const unsigned char* blob, int nst,
                                int stage_bytes, uint32_t idesc, int f4pt, int* phase) {
    const int tid = threadIdx.x;
    const int wid = tid >> 5;
    // prefill stage 0
    {
        const float4* s = (const float4*)blob;
        float4* d = (float4*)(sm + SM_B);
        for (int j = 0; j < f4pt; j++) d[tid + j * NTHR] = s[tid + j * NTHR];
    }
    FENCE_ASYNC();
    __syncthreads();

    const uint64_t ah = mk_desc(smb + SM_AHI);
    const uint64_t al = mk_desc(smb + SM_ALO);

    for (int c = 0; c < nst; c++) {
        float4 pre[8];
        if (c + 1 < nst) {
            const float4* s = (const float4*)(blob + (size_t)(c + 1) * stage_bytes);
            for (int j = 0; j < f4pt; j++) pre[j] = s[tid + j * NTHR];
        }
        if (wid == 0 && elect1()) {
            uint64_t bd = mk_desc(smb + SM_B + (uint32_t)(c & 1) * stage_bytes);
#pragma unroll
            for (int s2 = 0; s2 < 2; s2++) {
                int s = c * 2 + s2;
                uint32_t ao = (uint32_t)((s >> 2) * 1024 + (s & 3) * 2);
                uint32_t bo = (uint32_t)(s2 * 2);
                mma_ss(tmem, ah + ao, bd + bo, idesc, (uint32_t)((c | s2) != 0)); // hi*hi
                mma_ss(tmem, al + ao, bd + bo, idesc, 1u);                        // lo*hi
                mma_ss(tmem, ah + ao, bd + bo + 4, idesc, 1u);                    // hi*lo
            }
            TC_COMMIT(smb + 16 + (uint32_t)(c & 1) * 8);
        }
        if (c + 1 < nst) {
            if (c >= 1) {
                int b = (c - 1) & 1;
                MBAR_WAIT(smb + 16 + (uint32_t)b * 8, phase[b]);
                phase[b] ^= 1;
            }
            float4* d = (float4*)(sm + SM_B + (size_t)((c + 1) & 1) * stage_bytes);
            for (int j = 0; j < f4pt; j++) d[tid + j * NTHR] = pre[j];
        }
        FENCE_ASYNC();
        __syncthreads();
    }
    // drain outstanding commits (stages nst-2, nst-1)
    MBAR_WAIT(smb + 16 + 0, phase[0]); phase[0] ^= 1;
    MBAR_WAIT(smb + 16 + 8, phase[1]); phase[1] ^= 1;
}

// Epilogue for hidden GEMMs (N=256): read D, apply bias/act, split to A hi/lo.
// mode 0: v = d + b ; mode 1: v = relu(d + b) ; mode 2: v = y - (d + b)  (y in TMEM 256+)
static __device__ void epi_hidden(char* sm, uint32_t tmem, const float* __restrict__ bias, int mode) {
    const int tid = threadIdx.x, w = tid >> 5, lane = tid & 31;
    const int m = (w & 3) * 32 + lane, h = w >> 2;
    TC_FENCE_AFTER();
#pragma unroll 1
    for (int t = 0; t < 4; t++) {
        int n0 = h * 128 + t * 32;
        uint32_t d[32];
        LDTM32(d, tmem + (uint32_t)n0);
        uint32_t yv[32];
        if (mode == 2) LDTM32(yv, tmem + 256u + (uint32_t)n0);
        TC_WAIT_LD();
        float4 bq[8];
#pragma unroll
        for (int j = 0; j < 8; j++) bq[j] = ((const float4*)(bias + n0))[j];
        const float* bf = (const float*)bq;
#pragma unroll
        for (int q = 0; q < 8; q++) {
            uint32_t hp[2], lp[2];
#pragma unroll
            for (int e = 0; e < 2; e++) {
                unsigned short hs[2], ls[2];
#pragma unroll
                for (int u = 0; u < 2; u++) {
                    int r = q * 4 + e * 2 + u;
                    float v = __uint_as_float(d[r]) + bf[r];
                    if (mode == 1) v = fmaxf(v, 0.0f);
                    else if (mode == 2) v = __uint_as_float(yv[r]) - v;
                    split_bf(v, hs[u], ls[u]);
                }
                hp[e] = (uint32_t)hs[0] | ((uint32_t)hs[1] << 16);
                lp[e] = (uint32_t)ls[0] | ((uint32_t)ls[1] << 16);
            }
            uint32_t ad = a_addr(m, n0 + q * 4);
            *(uint2*)(sm + SM_AHI + ad) = make_uint2(hp[0], hp[1]);
            *(uint2*)(sm + SM_ALO + ad) = make_uint2(lp[0], lp[1]);
        }
    }
    TC_FENCE_BEFORE();
    FENCE_ASYNC();
    __syncthreads();
}

// Copy current activation (A hi+lo, fp32-reconstructed) into TMEM y (cols 256..511)
static __device__ void copy_y(char* sm, uint32_t tmem) {
    const int tid = threadIdx.x, w = tid >> 5, lane = tid & 31;
    const int m = (w & 3) * 32 + lane, h = w >> 2;
#pragma unroll 1
    for (int t = 0; t < 4; t++) {
        int n0 = h * 128 + t * 32;
        uint32_t u[32];
#pragma unroll
        for (int q = 0; q < 8; q++) {
            uint32_t ad = a_addr(m, n0 + q * 4);
            uint2 hv = *(const uint2*)(sm + SM_AHI + ad);
            uint2 lv = *(const uint2*)(sm + SM_ALO + ad);
            u[q * 4 + 0] = __float_as_uint(bfu2f(hv.x) + bfu2f(lv.x));
            u[q * 4 + 1] = __float_as_uint(bfu2f(hv.x >> 16) + bfu2f(lv.x >> 16));
            u[q * 4 + 2] = __float_as_uint(bfu2f(hv.y) + bfu2f(lv.y));
            u[q * 4 + 3] = __float_as_uint(bfu2f(hv.y >> 16) + bfu2f(lv.y >> 16));
        }
        STTM32(tmem + 256u + (uint32_t)n0, u);
    }
    TC_WAIT_ST();
    __syncthreads();
}

// Build initial A (hi/lo) from global x [TM rows x LAT]
static __device__ void build_initA(char* sm, const float* __restrict__ x, int row_base) {
    const int tid = threadIdx.x;
    const int m = tid >> 1, k0 = (tid & 1) * 64;
    const float4* xr = (const float4*)(x + (size_t)(row_base + m) * LAT + k0);
#pragma unroll
    for (int j = 0; j < 16; j++) {
        float4 v = xr[j];
        float vv[4] = {v.x, v.y, v.z, v.w};
        uint32_t hp[2], lp[2];
#pragma unroll
        for (int e = 0; e < 2; e++) {
            unsigned short hs[2], ls[2];
#pragma unroll
            for (int u = 0; u < 2; u++) split_bf(vv[e * 2 + u], hs[u], ls[u]);
            hp[e] = (uint32_t)hs[0] | ((uint32_t)hs[1] << 16);
            lp[e] = (uint32_t)ls[0] | ((uint32_t)ls[1] << 16);
        }
        uint32_t ad = a_addr(m, k0 + j * 4);
        *(uint2*)(sm + SM_AHI + ad) = make_uint2(hp[0], hp[1]);
        *(uint2*)(sm + SM_ALO + ad) = make_uint2(lp[0], lp[1]);
    }
    FENCE_ASYNC();
    __syncthreads();
}

// Final epilogue: out = D(cols 0..127) + b_final, STG fp32
static __device__ void epi_final(uint32_t tmem, const float* __restrict__ bias,
                                 float* __restrict__ out, int row_base) {
    const int tid = threadIdx.x, w = tid >> 5, lane = tid & 31;
    const int m = (w & 3) * 32 + lane, h = w >> 2;
    TC_FENCE_AFTER();
#pragma unroll 1
    for (int t = 0; t < 2; t++) {
        int n0 = h * 64 + t * 32;
        uint32_t d[32];
        LDTM32(d, tmem + (uint32_t)n0);
        TC_WAIT_LD();
        float4 bq[8];
#pragma unroll
        for (int j = 0; j < 8; j++) bq[j] = ((const float4*)(bias + n0))[j];
        const float* bf = (const float*)bq;
        float* orow = out + (size_t)(row_base + m) * ODIM + n0;
#pragma unroll
        for (int q = 0; q < 8; q++) {
            float4 o;
            o.x = __uint_as_float(d[q * 4 + 0]) + bf[q * 4 + 0];
            o.y = __uint_as_float(d[q * 4 + 1]) + bf[q * 4 + 1];
            o.z = __uint_as_float(d[q * 4 + 2]) + bf[q * 4 + 2];
            o.w = __uint_as_float(d[q * 4 + 3]) + bf[q * 4 + 3];
            *(float4*)(orow + q * 4) = o;
        }
    }
}

__global__ void __launch_bounds__(NTHR, 1)
inv_main(const float* __restrict__ x,
         const float* __restrict__ b_init, const float* __restrict__ bg1,
         const float* __restrict__ bg2,    const float* __restrict__ b_final,
         float* __restrict__ out) {
    extern __shared__ __align__(1024) char sm[];
    const uint32_t smb = smem_u32(sm);
    const int tid = threadIdx.x, wid = tid >> 5;
    const int row_base = blockIdx.x * TM;

    if (tid == 0) { MBAR_INIT(smb + 16); MBAR_INIT(smb + 24); }
    if (wid == 0) { TC_ALLOC(smb, 512); TC_RELINQ(); }
    __syncthreads();
    uint32_t tmem;
    asm volatile("ld.shared.b32 %0, [%1];" : "=r"(tmem) : "r"(smb));

    int phase[2] = {0, 0};

    build_initA(sm, x, row_base);
    // h = x @ W_init + b_init
    run_gemm(sm, smb, tmem, g_wblob + WB_INIT, LAT / KC, B_STG_H, IDESC_N256, 8, phase);
    epi_hidden(sm, tmem, b_init, 0);

    for (int b = 0; b < NBLK; b++) {
        copy_y(sm, tmem);  // y = current h
        const float* b1 = bg1 + b * HID;
        const float* b2 = bg2 + b * HID;
        for (int it = 0; it < NIT; it++) {
            run_gemm(sm, smb, tmem, g_wblob + WB_G1(b), HID / KC, B_STG_H, IDESC_N256, 8, phase);
            epi_hidden(sm, tmem, b1, 1);  // t = relu(x@W1 + b1)
            run_gemm(sm, smb, tmem, g_wblob + WB_G2(b), HID / KC, B_STG_H, IDESC_N256, 8, phase);
            epi_hidden(sm, tmem, b2, 2);  // x = y - (t@W2 + b2)
        }
    }

    // out = h @ W_final + b_final
    run_gemm(sm, smb, tmem, g_wblob + WB_FIN, HID / KC, B_STG_F, IDESC_N128, 4, phase);
    epi_final(tmem, b_final, out, row_base);

    __syncthreads();
    if (tid == 0) { MBAR_INVAL(smb + 16); MBAR_INVAL(smb + 24); }
    __syncthreads();
    if (wid == 0) { TC_DEALLOC(tmem, 512); }
}

extern "C" void kernel_launch(void* const* d_in, const int* in_sizes, int n_in,
                              void* d_out, int out_size) {
    const float* x       = (const float*)d_in[0];
    const float* W_init  = (const float*)d_in[1];
    const float* b_init  = (const float*)d_in[2];
    const float* Wg1     = (const float*)d_in[3];
    const float* bg1     = (const float*)d_in[4];
    const float* Wg2     = (const float*)d_in[5];
    const float* bg2     = (const float*)d_in[6];
    const float* W_final = (const float*)d_in[7];
    const float* b_final = (const float*)d_in[8];
    float* out = (float*)d_out;

    const int batch = in_sizes[0] / LAT;

    // weight preprocessing (cheap; runs inside the graph every replay)
    prep_w<<<(LAT * HID + 255) / 256, 256>>>(W_init, LAT, HID, WB_INIT);
    for (int b = 0; b < NBLK; b++) {
        prep_w<<<(HID * HID + 255) / 256, 256>>>(Wg1 + (size_t)b * HID * HID, HID, HID, WB_G1(b));
        prep_w<<<(HID * HID + 255) / 256, 256>>>(Wg2 + (size_t)b * HID * HID, HID, HID, WB_G2(b));
    }
    prep_w<<<(HID * ODIM + 255) / 256, 256>>>(W_final, HID, ODIM, WB_FIN);

    cudaFuncSetAttribute(inv_main, cudaFuncAttributeMaxDynamicSharedMemorySize, SM_BYTES);
    inv_main<<<batch / TM, NTHR, SM_BYTES>>>(x, b_init, bg1, bg2, b_final, out);
}

// round 9
// speedup vs baseline: 1.7526x; 1.7526x over previous
#include <cuda_runtime.h>
#include <cuda_bf16.h>
#include <cstdint>

#define HID   256
#define LAT   128
#define ODIM  128
#define NBLK  4
#define NIT   10
#define TM    128
#define NTHR  256

// SMEM layout (bytes): ctl [0]: tmem ptr; mbarriers full[0..2]@16/24/32, cm[0..2]@48/56/64, done@80
#define MB_FULL(s) (16u + (uint32_t)(s) * 8u)
#define MB_CM(s)   (48u + (uint32_t)(s) * 8u)
#define MB_DONE    80u
#define SM_Y     1024                    // y: [n/4][m][4] fp32 = 256*128*4 = 131072 B
#define SM_B     (1024 + 131072)         // B ring: 3 x 32 KB
#define B_SLOT   32768
#define SM_BYTES (SM_B + 3 * B_SLOT)     // 230400

// TMEM columns
#define TD   0u     // D: cols 0..255
#define TAH  256u   // A hi bf16x2: cols 256..383
#define TAL  384u   // A lo bf16x2: cols 384..511

// Pre-processed weights: per matrix, stages of 32 K; stage = exact SMEM image:
// N rows x 128B, bytes [0,64)=bf16 hi of 32 K, [64,128)=bf16 lo, SW128 swizzled.
#define WB_INIT  0u
#define WB_G1(b) (131072u + (unsigned)(b) * 262144u)
#define WB_G2(b) (1179648u + (unsigned)(b) * 262144u)
#define WB_FIN   2228224u
__device__ __align__(128) unsigned char g_wblob[2359296];

#define IDESC_N256 0x8400490u   // f32 acc, bf16xbf16, M=128, N=256
#define IDESC_N128 0x8200490u   // f32 acc, bf16xbf16, M=128, N=128
#define TOTAL_STAGES 652        // 4 (init) + 80*8 (hidden) + 8 (final)

static constexpr uint64_t DESC_BASE_SW128 =
    (uint64_t(2) << 61) | (uint64_t(1) << 46) | (uint64_t(64) << 32) | (uint64_t(1) << 16);

// tcgen05 is arch-specific: stub it for the compute_103 family ptxas pass.
#if defined(__CUDA_ARCH__) && \
    (defined(__CUDA_ARCH_FEAT_SM103_ALL) || defined(__CUDA_ARCH_FEAT_SM100_ALL) || \
     defined(__CUDA_ARCH_FEAT_SM101_ALL) || defined(__CUDA_ARCH_SPECIFIC__))
#define TC_OK 1
#else
#define TC_OK 0
#endif

static __device__ __forceinline__ uint32_t smem_u32(const void* p) {
    uint32_t a;
    asm("{ .reg .u64 t; cvta.to.shared.u64 t, %1; cvt.u32.u64 %0, t; }" : "=r"(a) : "l"(p));
    return a;
}
static __device__ __forceinline__ uint32_t elect1() {
    uint32_t p;
    asm volatile("{ .reg .pred p; elect.sync _|p, 0xFFFFFFFF; selp.b32 %0, 1, 0, p; }" : "=r"(p));
    return p;
}
static __device__ __forceinline__ uint64_t mk_desc(uint32_t addr) {
    return DESC_BASE_SW128 | ((uint64_t)(addr >> 4) & 0x3FFF);
}
static __device__ __forceinline__ uint32_t cvt_bf2(float v0, float v1) {
    uint32_t r;  // lo half = v0, hi half = v1
    asm("cvt.rn.bf16x2.f32 %0, %1, %2;" : "=r"(r) : "f"(v1), "f"(v0));
    return r;
}
static __device__ __forceinline__ float bfu2f(uint32_t us) {
    return __uint_as_float((us & 0xFFFFu) << 16);
}

#define MBAR_INIT(a) \
    asm volatile("mbarrier.init.shared.b64 [%0], %1;" :: "r"(a), "r"(1u) : "memory")
#define MBAR_INVAL(a) \
    asm volatile("mbarrier.inval.shared.b64 [%0];" :: "r"(a) : "memory")
#define MBAR_EXPECT_TX(a, bytes) \
    asm volatile("mbarrier.arrive.expect_tx.shared.b64 _, [%0], %1;" \
                 :: "r"(a), "r"((uint32_t)(bytes)) : "memory")
#define MBAR_WAIT(a, ph) do {                                                          \
    asm volatile("{\n\t.reg .pred P;\nWL_%=:\n\t"                                      \
        "mbarrier.try_wait.parity.acquire.cta.shared::cta.b64 P, [%0], %1, 0x989680;\n\t" \
        "@P bra.uni WD_%=;\n\tbra.uni WL_%=;\nWD_%=:\n\t}"                             \
        :: "r"(a), "r"((uint32_t)(ph)) : "memory");                                    \
} while (0)
static __device__ __forceinline__ void bulk_g2s(uint32_t dst, const void* src,
                                                uint32_t bytes, uint32_t mbar) {
    asm volatile(
        "cp.async.bulk.shared::cluster.global.mbarrier::complete_tx::bytes [%0], [%1], %2, [%3];"
        :: "r"(dst), "l"(src), "r"(bytes), "r"(mbar) : "memory");
}

#if TC_OK
static __device__ __forceinline__ void mma_ts(uint32_t d, uint32_t a, uint64_t bd,
                                              uint32_t idesc, uint32_t en) {
    asm volatile(
        "{\n\t.reg .pred p;\n\tsetp.ne.u32 p, %4, 0;\n\t"
        "tcgen05.mma.cta_group::1.kind::f16 [%0], [%1], %2, %3, {%5, %5, %5, %5}, p;\n\t}"
        :: "r"(d), "r"(a), "l"(bd), "r"(idesc), "r"(en), "r"(0u) : "memory");
}
#define TC_COMMIT(mb) \
    asm volatile("tcgen05.commit.cta_group::1.mbarrier::arrive::one.shared::cluster.b64 [%0];" \
                 :: "r"(mb) : "memory")
#define TC_FENCE_AFTER()   asm volatile("tcgen05.fence::after_thread_sync;" ::: "memory")
#define TC_FENCE_BEFORE()  asm volatile("tcgen05.fence::before_thread_sync;" ::: "memory")
#define TC_WAIT_LD()   asm volatile("tcgen05.wait::ld.sync.aligned;" ::: "memory")
#define TC_WAIT_ST()   asm volatile("tcgen05.wait::st.sync.aligned;" ::: "memory")
#define TC_ALLOC(sa, n) \
    asm volatile("tcgen05.alloc.cta_group::1.sync.aligned.shared::cta.b32 [%0], %1;" \
                 :: "r"(sa), "r"((uint32_t)(n)) : "memory")
#define TC_DEALLOC(t, n) \
    asm volatile("tcgen05.dealloc.cta_group::1.sync.aligned.b32 %0, %1;" :: "r"(t), "r"((uint32_t)(n)))
#define TC_RELINQ() \
    asm volatile("tcgen05.relinquish_alloc_permit.cta_group::1.sync.aligned;")

#define LDTM32(r, a)                                                                    \
    asm volatile("tcgen05.ld.sync.aligned.32x32b.x32.b32 "                              \
        "{%0,%1,%2,%3,%4,%5,%6,%7,%8,%9,%10,%11,%12,%13,%14,%15,"                       \
        "%16,%17,%18,%19,%20,%21,%22,%23,%24,%25,%26,%27,%28,%29,%30,%31}, [%32];"      \
        : "=r"((r)[0]),"=r"((r)[1]),"=r"((r)[2]),"=r"((r)[3]),"=r"((r)[4]),"=r"((r)[5]),\
          "=r"((r)[6]),"=r"((r)[7]),"=r"((r)[8]),"=r"((r)[9]),"=r"((r)[10]),"=r"((r)[11]),\
          "=r"((r)[12]),"=r"((r)[13]),"=r"((r)[14]),"=r"((r)[15]),"=r"((r)[16]),"=r"((r)[17]),\
          "=r"((r)[18]),"=r"((r)[19]),"=r"((r)[20]),"=r"((r)[21]),"=r"((r)[22]),"=r"((r)[23]),\
          "=r"((r)[24]),"=r"((r)[25]),"=r"((r)[26]),"=r"((r)[27]),"=r"((r)[28]),"=r"((r)[29]),\
          "=r"((r)[30]),"=r"((r)[31]) : "r"(a))

#define STTM16(a, r)                                                                    \
    asm volatile("tcgen05.st.sync.aligned.32x32b.x16.b32 [%0], "                        \
        "{%1,%2,%3,%4,%5,%6,%7,%8,%9,%10,%11,%12,%13,%14,%15,%16};"                     \
        :: "r"(a), "r"((r)[0]),"r"((r)[1]),"r"((r)[2]),"r"((r)[3]),"r"((r)[4]),"r"((r)[5]),\
           "r"((r)[6]),"r"((r)[7]),"r"((r)[8]),"r"((r)[9]),"r"((r)[10]),"r"((r)[11]),   \
           "r"((r)[12]),"r"((r)[13]),"r"((r)[14]),"r"((r)[15]) : "memory")

#define STTM32(a, r)                                                                    \
    asm volatile("tcgen05.st.sync.aligned.32x32b.x32.b32 [%0], "                        \
        "{%1,%2,%3,%4,%5,%6,%7,%8,%9,%10,%11,%12,%13,%14,%15,%16,"                      \
        "%17,%18,%19,%20,%21,%22,%23,%24,%25,%26,%27,%28,%29,%30,%31,%32};"             \
        :: "r"(a), "r"((r)[0]),"r"((r)[1]),"r"((r)[2]),"r"((r)[3]),"r"((r)[4]),"r"((r)[5]),\
           "r"((r)[6]),"r"((r)[7]),"r"((r)[8]),"r"((r)[9]),"r"((r)[10]),"r"((r)[11]),   \
           "r"((r)[12]),"r"((r)[13]),"r"((r)[14]),"r"((r)[15]),"r"((r)[16]),"r"((r)[17]),\
           "r"((r)[18]),"r"((r)[19]),"r"((r)[20]),"r"((r)[21]),"r"((r)[22]),"r"((r)[23]),\
           "r"((r)[24]),"r"((r)[25]),"r"((r)[26]),"r"((r)[27]),"r"((r)[28]),"r"((r)[29]),\
           "r"((r)[30]),"r"((r)[31]) : "memory")
#else
static __device__ __forceinline__ void mma_ts(uint32_t, uint32_t, uint64_t, uint32_t, uint32_t) {}
#define TC_COMMIT(mb)      do { (void)(mb); } while (0)
#define TC_FENCE_AFTER()   do {} while (0)
#define TC_FENCE_BEFORE()  do {} while (0)
#define TC_WAIT_LD()       do {} while (0)
#define TC_WAIT_ST()       do {} while (0)
#define TC_ALLOC(sa, n)    do { (void)(sa); (void)(n); } while (0)
#define TC_DEALLOC(t, n)   do { (void)(t); (void)(n); } while (0)
#define TC_RELINQ()        do {} while (0)
#define LDTM32(r, a)       do { _Pragma("unroll") for (int _i = 0; _i < 32; _i++) (r)[_i] = 0u; (void)(a); } while (0)
#define STTM16(a, r)       do { (void)(a); (void)(r); } while (0)
#define STTM32(a, r)       do { (void)(a); (void)(r); } while (0)
#endif

// global stage index -> (blob ptr, bytes)
static __device__ __forceinline__ void stage_info(int i, const unsigned char** p, uint32_t* nb) {
    if (i < 4) { *p = g_wblob + WB_INIT + (size_t)i * 32768; *nb = 32768u; return; }
    i -= 4;
    if (i < 640) {
        int gg = i >> 3, s = i & 7;
        int b = gg / 20, r = gg % 20;
        unsigned base = (r & 1) ? WB_G2(b) : WB_G1(b);
        *p = g_wblob + base + (size_t)s * 32768; *nb = 32768u; return;
    }
    i -= 640;
    *p = g_wblob + WB_FIN + (size_t)i * 16384; *nb = 16384u;
}

// ---------------- merged weight prep ----------------
__global__ void prep_all(const float* __restrict__ Wi, const float* __restrict__ Wg1,
                         const float* __restrict__ Wg2, const float* __restrict__ Wf) {
    int gid = blockIdx.x * blockDim.x + threadIdx.x;
    if (gid >= 589824) return;
    const float* W; int N; unsigned off; int e;
    if (gid < 32768)       { W = Wi; N = HID; off = WB_INIT; e = gid; }
    else if (gid < 294912) { int j = gid - 32768;  int b = j >> 16; e = j & 65535;
                             W = Wg1 + (size_t)b * 65536; N = HID; off = WB_G1(b); }
    else if (gid < 557056) { int j = gid - 294912; int b = j >> 16; e = j & 65535;
                             W = Wg2 + (size_t)b * 65536; N = HID; off = WB_G2(b); }
    else                   { e = gid - 557056; W = Wf; N = ODIM; off = WB_FIN; }
    int k = e / N, n = e % N;
    float w = W[e];
    __nv_bfloat16 hb = __float2bfloat16(w);
    float hf = __bfloat162float(hb);
    __nv_bfloat16 lb = __float2bfloat16(w - hf);
    int stage = k >> 5, kl = k & 31;
    unsigned row = (unsigned)((n >> 3) * 1024 + (n & 7) * 128);
    unsigned oh = row + kl * 2;
    unsigned ol = row + (32 + kl) * 2;
    oh ^= (oh >> 3) & 0x70;
    ol ^= (ol >> 3) & 0x70;
    unsigned char* sb = g_wblob + off + (size_t)stage * ((size_t)N * 128);
    *(unsigned short*)(sb + oh) = *reinterpret_cast<unsigned short*>(&hb);
    *(unsigned short*)(sb + ol) = *reinterpret_cast<unsigned short*>(&lb);
}

// ---------------- GEMM driver: MMA + B-ring, single elected thread ----------------
static __device__ void do_gemm(uint32_t smb, uint32_t tmem, int base, int nst, uint32_t idesc,
                               int g, uint32_t& fph, uint32_t& cph, uint32_t& pend) {
    if ((threadIdx.x >> 5) == 0) {
        if (elect1()) {
            TC_FENCE_AFTER();
            for (int c = 0; c < nst; c++) {
                int idx = base + c;
                int s = idx % 3;
                MBAR_WAIT(smb + MB_FULL(s), (fph >> s) & 1);
                fph ^= 1u << s;
                uint64_t bd = mk_desc(smb + SM_B + (uint32_t)s * B_SLOT);
#pragma unroll
                for (int s2 = 0; s2 < 2; s2++) {
                    uint32_t ks = (uint32_t)(c * 2 + s2);
                    uint32_t ah = tmem + TAH + ks * 8;
                    uint32_t al = tmem + TAL + ks * 8;
                    uint32_t bo = (uint32_t)(s2 * 2);
                    mma_ts(tmem + TD, ah, bd + bo,     idesc, (uint32_t)((c | s2) != 0));
                    mma_ts(tmem + TD, al, bd + bo,     idesc, 1u);
                    mma_ts(tmem + TD, ah, bd + bo + 4, idesc, 1u);
                }
                TC_COMMIT(smb + MB_CM(s));
                pend |= 1u << s;
                if (c == nst - 1) TC_COMMIT(smb + MB_DONE);
                int nx = idx + 2;
                if (nx < TOTAL_STAGES) {
                    int sx = nx % 3;
                    if ((pend >> sx) & 1) {
                        MBAR_WAIT(smb + MB_CM(sx), (cph >> sx) & 1);
                        cph ^= 1u << sx;
                    }
                    const unsigned char* p; uint32_t nb;
                    stage_info(nx, &p, &nb);
                    MBAR_EXPECT_TX(smb + MB_FULL(sx), nb);
                    bulk_g2s(smb + SM_B + (uint32_t)sx * B_SLOT, p, nb, smb + MB_FULL(sx));
                }
            }
        }
    }
    MBAR_WAIT(smb + MB_DONE, g & 1);
    TC_FENCE_AFTER();
}

// ---------------- epilogue (hidden, N=256) ----------------
// mode 0: v=d+b; 1: v=relu(d+b); 2: v=y-(d+b). wy: also write v into SMEM y.
static __device__ void epi_hidden(char* sm, uint32_t tmem, const float* __restrict__ bias,
                                  int mode, int wy) {
    const int tid = threadIdx.x, w = tid >> 5, lane = tid & 31;
    const int m = (w & 3) * 32 + lane, h = w >> 2;
#pragma unroll 1
    for (int t = 0; t < 4; t++) {
        int n0 = h * 128 + t * 32;
        uint32_t d[32];
        LDTM32(d, tmem + TD + (uint32_t)n0);
        TC_WAIT_LD();
        float v[32];
#pragma unroll
        for (int q = 0; q < 8; q++) {
            float4 bq = ((const float4*)(bias + n0))[q];
            v[q*4+0] = __uint_as_float(d[q*4+0]) + bq.x;
            v[q*4+1] = __uint_as_float(d[q*4+1]) + bq.y;
            v[q*4+2] = __uint_as_float(d[q*4+2]) + bq.z;
            v[q*4+3] = __uint_as_float(d[q*4+3]) + bq.w;
        }
        if (mode == 1) {
#pragma unroll
            for (int i = 0; i < 32; i++) v[i] = fmaxf(v[i], 0.0f);
        } else if (mode == 2) {
#pragma unroll
            for (int q = 0; q < 8; q++) {
                float4 yq = *(const float4*)(sm + SM_Y + (size_t)((n0 >> 2) + q) * 2048 + (size_t)m * 16);
                v[q*4+0] = yq.x - v[q*4+0];
                v[q*4+1] = yq.y - v[q*4+1];
                v[q*4+2] = yq.z - v[q*4+2];
                v[q*4+3] = yq.w - v[q*4+3];
            }
        }
        if (wy) {
#pragma unroll
            for (int q = 0; q < 8; q++)
                *(float4*)(sm + SM_Y + (size_t)((n0 >> 2) + q) * 2048 + (size_t)m * 16) =
                    make_float4(v[q*4+0], v[q*4+1], v[q*4+2], v[q*4+3]);
        }
        uint32_t hi[16], lo[16];
#pragma unroll
        for (int p = 0; p < 16; p++) {
            float a0 = v[2*p], a1 = v[2*p+1];
            uint32_t hh = cvt_bf2(a0, a1);
            float l0 = a0 - bfu2f(hh);
            float l1 = a1 - bfu2f(hh >> 16);
            hi[p] = hh;
            lo[p] = cvt_bf2(l0, l1);
        }
        STTM16(tmem + TAH + (uint32_t)(n0 >> 1), hi);
        STTM16(tmem + TAL + (uint32_t)(n0 >> 1), lo);
    }
    TC_WAIT_ST();
    TC_FENCE_BEFORE();
    __syncthreads();
}

// ---------------- initial A from global x ----------------
static __device__ void build_initA(const float* __restrict__ x, uint32_t tmem, int row_base) {
    const int tid = threadIdx.x, w = tid >> 5, lane = tid & 31;
    const int m = (w & 3) * 32 + lane, khalf = w >> 2;
    const int k0 = khalf * 64;
    const float4* xr = (const float4*)(x + (size_t)(row_base + m) * LAT + k0);
    float xv[64];
#pragma unroll
    for (int j = 0; j < 16; j++) {
        float4 q = xr[j];
        xv[j*4+0] = q.x; xv[j*4+1] = q.y; xv[j*4+2] = q.z; xv[j*4+3] = q.w;
    }
    uint32_t hi[32], lo[32];
#pragma unroll
    for (int p = 0; p < 32; p++) {
        float a0 = xv[2*p], a1 = xv[2*p+1];
        uint32_t hh = cvt_bf2(a0, a1);
        float l0 = a0 - bfu2f(hh);
        float l1 = a1 - bfu2f(hh >> 16);
        hi[p] = hh;
        lo[p] = cvt_bf2(l0, l1);
    }
    STTM32(tmem + TAH + (uint32_t)(khalf * 32), hi);
    STTM32(tmem + TAL + (uint32_t)(khalf * 32), lo);
    TC_WAIT_ST();
    TC_FENCE_BEFORE();
    __syncthreads();
}

// ---------------- final epilogue: out = D + b_final ----------------
static __device__ void epi_final(uint32_t tmem, const float* __restrict__ bias,
                                 float* __restrict__ out, int row_base) {
    const int tid = threadIdx.x, w = tid >> 5, lane = tid & 31;
    const int m = (w & 3) * 32 + lane, h = w >> 2;
#pragma unroll 1
    for (int t = 0; t < 2; t++) {
        int n0 = h * 64 + t * 32;
        uint32_t d[32];
        LDTM32(d, tmem + TD + (uint32_t)n0);
        TC_WAIT_LD();
        float* orow = out + (size_t)(row_base + m) * ODIM + n0;
#pragma unroll
        for (int q = 0; q < 8; q++) {
            float4 bq = ((const float4*)(bias + n0))[q];
            float4 o;
            o.x = __uint_as_float(d[q*4+0]) + bq.x;
            o.y = __uint_as_float(d[q*4+1]) + bq.y;
            o.z = __uint_as_float(d[q*4+2]) + bq.z;
            o.w = __uint_as_float(d[q*4+3]) + bq.w;
            *(float4*)(orow + q * 4) = o;
        }
    }
}

__global__ void __launch_bounds__(NTHR, 1)
inv_main(const float* __restrict__ x,
         const float* __restrict__ b_init, const float* __restrict__ bg1,
         const float* __restrict__ bg2,    const float* __restrict__ b_final,
         float* __restrict__ out) {
    extern __shared__ __align__(1024) char sm[];
    const uint32_t smb = smem_u32(sm);
    const int tid = threadIdx.x;
    const int row_base = blockIdx.x * TM;

    if (tid == 0) {
        MBAR_INIT(smb + MB_FULL(0)); MBAR_INIT(smb + MB_FULL(1)); MBAR_INIT(smb + MB_FULL(2));
        MBAR_INIT(smb + MB_CM(0));   MBAR_INIT(smb + MB_CM(1));   MBAR_INIT(smb + MB_CM(2));
        MBAR_INIT(smb + MB_DONE);
    }
    if ((tid >> 5) == 0) { TC_ALLOC(smb, 512); TC_RELINQ(); }
    __syncthreads();
    uint32_t tmem;
    asm volatile("ld.shared.b32 %0, [%1];" : "=r"(tmem) : "r"(smb));

    uint32_t fph = 0, cph = 0, pend = 0;

    // bootstrap: stages 0,1 into slots 0,1
    if ((tid >> 5) == 0 && elect1()) {
#pragma unroll
        for (int i = 0; i < 2; i++) {
            const unsigned char* p; uint32_t nb;
            stage_info(i, &p, &nb);
            MBAR_EXPECT_TX(smb + MB_FULL(i), nb);
            bulk_g2s(smb + SM_B + (uint32_t)i * B_SLOT, p, nb, smb + MB_FULL(i));
        }
    }

    build_initA(x, tmem, row_base);

    int g = 0, base = 0;
    do_gemm(smb, tmem, base, 4, IDESC_N256, g, fph, cph, pend);
    g++; base += 4;
    epi_hidden(sm, tmem, b_init, 0, 1);   // h = x@Wi + bi; write y

    for (int b = 0; b < NBLK; b++) {
        const float* b1 = bg1 + b * HID;
        const float* b2 = bg2 + b * HID;
        for (int it = 0; it < NIT; it++) {
            do_gemm(smb, tmem, base, 8, IDESC_N256, g, fph, cph, pend);
            g++; base += 8;
            epi_hidden(sm, tmem, b1, 1, 0);                       // t = relu(x@W1+b1)
            do_gemm(smb, tmem, base, 8, IDESC_N256, g, fph, cph, pend);
            g++; base += 8;
            epi_hidden(sm, tmem, b2, 2, (it == NIT - 1) ? 1 : 0); // x = y-(t@W2+b2)
        }
    }

    do_gemm(smb, tmem, base, 8, IDESC_N128, g, fph, cph, pend);
    epi_final(tmem, b_final, out, row_base);

    __syncthreads();
    if (tid == 0) {
        MBAR_INVAL(smb + MB_FULL(0)); MBAR_INVAL(smb + MB_FULL(1)); MBAR_INVAL(smb + MB_FULL(2));
        MBAR_INVAL(smb + MB_CM(0));   MBAR_INVAL(smb + MB_CM(1));   MBAR_INVAL(smb + MB_CM(2));
        MBAR_INVAL(smb + MB_DONE);
    }
    __syncthreads();
    if ((tid >> 5) == 0) { TC_DEALLOC(tmem, 512); }
}

extern "C" void kernel_launch(void* const* d_in, const int* in_sizes, int n_in,
                              void* d_out, int out_size) {
    const float* x       = (const float*)d_in[0];
    const float* W_init  = (const float*)d_in[1];
    const float* b_init  = (const float*)d_in[2];
    const float* Wg1     = (const float*)d_in[3];
    const float* bg1     = (const float*)d_in[4];
    const float* Wg2     = (const float*)d_in[5];
    const float* bg2     = (const float*)d_in[6];
    const float* W_final = (const float*)d_in[7];
    const float* b_final = (const float*)d_in[8];
    float* out = (float*)d_out;

    const int batch = in_sizes[0] / LAT;

    prep_all<<<(589824 + 255) / 256, 256>>>(W_init, Wg1, Wg2, W_final);

    cudaFuncSetAttribute(inv_main, cudaFuncAttributeMaxDynamicSharedMemorySize, SM_BYTES);
    inv_main<<<batch / TM, NTHR, SM_BYTES>>>(x, b_init, bg1, bg2, b_final, out);
}